// round 3
// baseline (speedup 1.0000x reference)
#include <cuda_runtime.h>

#define N_NODES 50000
#define IN_F    128
#define OUT_F   64
#define HEADS   2
#define ALPHA   0.2f

typedef unsigned long long u64;

// dst-side data colocated so the gather and the atomic hit the same 32B sector
struct __align__(16) NodeD { float2 sj; float2 c; };

__device__ float  g_v[512];          // [which(i/j)][head][128]
__device__ float2 g_si[N_NODES];
__device__ NodeD  g_nd[N_NODES];
__device__ float  g_Z[2];

// ---------------------------------------------------------------------------
// 1) v = W @ a (both halves, both heads); also zero g_Z for this launch
__global__ void prep_v_kernel(const float* __restrict__ W,
                              const float* __restrict__ a) {
    int t = threadIdx.x;            // 512 threads
    if (t < 2) g_Z[t] = 0.0f;
    int which = t >> 8;
    int h     = (t >> 7) & 1;
    int i     = t & 127;
    const float* wrow = W + h * (IN_F * OUT_F) + i * OUT_F;
    const float* av   = a + h * (2 * OUT_F) + which * OUT_F;
    float s = 0.f;
#pragma unroll 16
    for (int o = 0; o < OUT_F; o++) s += wrow[o] * av[o];
    g_v[which * 256 + h * 128 + i] = s;
}

// ---------------------------------------------------------------------------
// 2) per-node scores; writes g_si and g_nd = {sj, 0,0} (c zeroed here)
__global__ void __launch_bounds__(256) node_s_kernel(const float* __restrict__ x, int N) {
    __shared__ float vsm[512];
    int tid = threadIdx.x;
    vsm[tid]       = g_v[tid];
    vsm[tid + 256] = g_v[tid + 256];
    __syncthreads();

    int warp = tid >> 5, lane = tid & 31;
    int n = blockIdx.x * 8 + warp;
    if (n >= N) return;

    float4 xv = ((const float4*)x)[(size_t)n * 32 + lane];
    const float4* v4 = (const float4*)vsm;
    float4 vi0 = v4[lane];
    float4 vi1 = v4[32 + lane];
    float4 vj0 = v4[64 + lane];
    float4 vj1 = v4[96 + lane];

    float si0 = xv.x*vi0.x + xv.y*vi0.y + xv.z*vi0.z + xv.w*vi0.w;
    float si1 = xv.x*vi1.x + xv.y*vi1.y + xv.z*vi1.z + xv.w*vi1.w;
    float sj0 = xv.x*vj0.x + xv.y*vj0.y + xv.z*vj0.z + xv.w*vj0.w;
    float sj1 = xv.x*vj1.x + xv.y*vj1.y + xv.z*vj1.z + xv.w*vj1.w;

#pragma unroll
    for (int off = 16; off; off >>= 1) {
        si0 += __shfl_xor_sync(0xffffffffu, si0, off);
        si1 += __shfl_xor_sync(0xffffffffu, si1, off);
        sj0 += __shfl_xor_sync(0xffffffffu, sj0, off);
        sj1 += __shfl_xor_sync(0xffffffffu, sj1, off);
    }
    if (lane == 0) {
        g_si[n] = make_float2(si0, si1);
        float4 nd = make_float4(sj0, sj1, 0.f, 0.f);
        *(float4*)&g_nd[n] = nd;
    }
}

// ---------------------------------------------------------------------------
// 3) edge pass: 4 edges/thread (int4 index loads), gathers batched for MLP,
//    one red.add.v2.f32 per edge to the SAME sector as the sj gather.
__device__ __forceinline__ void edge_one(int src, int dst,
                                         const float2 si, const float2 sj) {
    float e0 = si.x + sj.x;
    float e1 = si.y + sj.y;
    e0 = e0 > 0.f ? e0 : ALPHA * e0;
    e1 = e1 > 0.f ? e1 : ALPHA * e1;
    float w0 = __expf(e0);
    float w1 = __expf(e1);
    asm volatile("red.add.v2.f32 [%0], {%1, %2};"
                 :: "l"(&g_nd[dst].c), "f"(w0), "f"(w1) : "memory");
}

__global__ void __launch_bounds__(256) edge_kernel(const int* __restrict__ ei, int E) {
    int k = (blockIdx.x * blockDim.x + threadIdx.x) * 4;
    if (k + 3 < E) {
        int4 s4 = *(const int4*)(ei + k);
        int4 d4 = *(const int4*)(ei + E + k);
        // batch the gathers first (MLP = 8)
        float2 si0 = g_si[s4.x], si1 = g_si[s4.y], si2 = g_si[s4.z], si3 = g_si[s4.w];
        float2 sj0 = g_nd[d4.x].sj, sj1 = g_nd[d4.y].sj,
               sj2 = g_nd[d4.z].sj, sj3 = g_nd[d4.w].sj;
        edge_one(s4.x, d4.x, si0, sj0);
        edge_one(s4.y, d4.y, si1, sj1);
        edge_one(s4.z, d4.z, si2, sj2);
        edge_one(s4.w, d4.w, si3, sj3);
    } else {
        for (; k < E; k++) {
            int src = ei[k], dst = ei[E + k];
            edge_one(src, dst, g_si[src], g_nd[dst].sj);
        }
    }
}

// ---------------------------------------------------------------------------
// 4) Z_h = sum_n c[n,h]
__global__ void __launch_bounds__(256) zred_kernel(int n) {
    float z0 = 0.f, z1 = 0.f;
    for (int i = blockIdx.x * blockDim.x + threadIdx.x; i < n;
         i += gridDim.x * blockDim.x) {
        float2 c = g_nd[i].c;
        z0 += c.x;
        z1 += c.y;
    }
#pragma unroll
    for (int off = 16; off; off >>= 1) {
        z0 += __shfl_xor_sync(0xffffffffu, z0, off);
        z1 += __shfl_xor_sync(0xffffffffu, z1, off);
    }
    __shared__ float s0[8], s1[8];
    int warp = threadIdx.x >> 5, lane = threadIdx.x & 31;
    if (lane == 0) { s0[warp] = z0; s1[warp] = z1; }
    __syncthreads();
    if (threadIdx.x == 0) {
        float t0 = 0.f, t1 = 0.f;
#pragma unroll
        for (int w = 0; w < 8; w++) { t0 += s0[w]; t1 += s1[w]; }
        atomicAdd(&g_Z[0], t0);
        atomicAdd(&g_Z[1], t1);
    }
}

// ---------------------------------------------------------------------------
// 5) out = (x @ W) * c/Z  — packed f32x2 FFMA GEMM.
//    x tile stored DUPLICATED in smem (float2(v,v)) so LDS.64 gives a packed
//    broadcast multiplicand with zero pack instructions; consecutive ws floats
//    reinterpret directly as packed column pairs.
__device__ __forceinline__ u64 f2fma(u64 a, u64 b, u64 c) {
    u64 d;
    asm("fma.rn.f32x2 %0, %1, %2, %3;" : "=l"(d) : "l"(a), "l"(b), "l"(c));
    return d;
}
__device__ __forceinline__ float2 u2f(u64 v) {
    float2 f;
    asm("mov.b64 {%0, %1}, %2;" : "=f"(f.x), "=f"(f.y) : "l"(v));
    return f;
}

__global__ void __launch_bounds__(256, 1) out_gemm_kernel(const float* __restrict__ x,
                                                          const float* __restrict__ W,
                                                          float* __restrict__ out, int N) {
    extern __shared__ char smem[];
    float2* xsd = (float2*)smem;                 // [128][128] duplicated, 128 KB
    float*  ws  = (float*)(smem + 131072);       // [128][128], 64 KB

    int tid = threadIdx.x;
    int n0 = blockIdx.x * 128;

    // stage W: W[h][i][o] -> ws[i][h*64+o]
    for (int idx = tid; idx < HEADS * IN_F * OUT_F; idx += 256) {
        int h = idx >> 13;
        int i = (idx >> 6) & 127;
        int o = idx & 63;
        ws[i * 128 + h * 64 + o] = W[idx];
    }
    // stage x tile duplicated (zero-padded past N)
    for (int idx = tid; idx < 128 * 128; idx += 256) {
        int r = idx >> 7, kk = idx & 127;
        int n = n0 + r;
        float v = (n < N) ? x[(size_t)n * 128 + kk] : 0.f;
        xsd[r * 128 + kk] = make_float2(v, v);
    }
    __syncthreads();

    int tr = tid >> 4, tc = tid & 15;   // 16x16 threads, 8 rows x 8 cols each
    u64 acc[8][4];
#pragma unroll
    for (int i = 0; i < 8; i++)
#pragma unroll
        for (int j = 0; j < 4; j++) acc[i][j] = 0ull;

#pragma unroll 2
    for (int k = 0; k < 128; k++) {
        u64 ap[8];
#pragma unroll
        for (int i = 0; i < 8; i++)
            ap[i] = *(const u64*)&xsd[(tr * 8 + i) * 128 + k];
        ulonglong2 b01 = *(const ulonglong2*)&ws[k * 128 + tc * 8];
        ulonglong2 b23 = *(const ulonglong2*)&ws[k * 128 + tc * 8 + 4];
        u64 bp[4] = {b01.x, b01.y, b23.x, b23.y};
#pragma unroll
        for (int i = 0; i < 8; i++)
#pragma unroll
            for (int j = 0; j < 4; j++)
                acc[i][j] = f2fma(ap[i], bp[j], acc[i][j]);
    }

    float rz = 1.0f / ((tc < 8) ? g_Z[0] : g_Z[1]);
#pragma unroll
    for (int i = 0; i < 8; i++) {
        int n = n0 + tr * 8 + i;
        if (n < N) {
            float2 cc = g_nd[n].c;
            float scl = ((tc < 8) ? cc.x : cc.y) * rz;
            float2 p0 = u2f(acc[i][0]), p1 = u2f(acc[i][1]);
            float2 p2 = u2f(acc[i][2]), p3 = u2f(acc[i][3]);
            float4 o0 = make_float4(p0.x * scl, p0.y * scl, p1.x * scl, p1.y * scl);
            float4 o1 = make_float4(p2.x * scl, p2.y * scl, p3.x * scl, p3.y * scl);
            float* orow = out + (size_t)n * 128 + tc * 8;
            *(float4*)orow       = o0;
            *(float4*)(orow + 4) = o1;
        }
    }
}

// ---------------------------------------------------------------------------
extern "C" void kernel_launch(void* const* d_in, const int* in_sizes, int n_in,
                              void* d_out, int out_size) {
    const float* x  = (const float*)d_in[0];
    const float* W  = (const float*)d_in[1];
    const float* a  = (const float*)d_in[2];
    const int*   ei = (const int*)d_in[3];
    float* out = (float*)d_out;

    int N = in_sizes[0] / IN_F;
    if (N > N_NODES) N = N_NODES;
    int E = in_sizes[3] / 2;

    prep_v_kernel<<<1, 512>>>(W, a);
    node_s_kernel<<<(N + 7) / 8, 256>>>(x, N);
    edge_kernel<<<((E + 3) / 4 + 255) / 256, 256>>>(ei, E);
    zred_kernel<<<120, 256>>>(N);

    const int smem_bytes = 128 * 128 * 8 + 128 * 128 * 4;  // 192 KB
    cudaFuncSetAttribute(out_gemm_kernel,
                         cudaFuncAttributeMaxDynamicSharedMemorySize, smem_bytes);
    out_gemm_kernel<<<(N + 127) / 128, 256, smem_bytes>>>(x, W, out, N);
}

// round 4
// speedup vs baseline: 1.3928x; 1.3928x over previous
#include <cuda_runtime.h>

#define N_NODES 50000
#define IN_F    128
#define OUT_F   64
#define HEADS   2
#define ALPHA   0.2f

__device__ float  g_v[512];          // [which(i/j)][head][128]
__device__ float2 g_si[N_NODES];
__device__ float2 g_sj[N_NODES];
__device__ float2 g_c[N_NODES];      // per-node sum of exp(e) per head
__device__ float  g_Z[2];            // global softmax denominator per head

// ---------------------------------------------------------------------------
// 1) v = W @ a (both halves, both heads); also zero g_Z
__global__ void prep_v_kernel(const float* __restrict__ W,
                              const float* __restrict__ a) {
    int t = threadIdx.x;            // 512 threads
    if (t < 2) g_Z[t] = 0.0f;
    int which = t >> 8;
    int h     = (t >> 7) & 1;
    int i     = t & 127;
    const float* wrow = W + h * (IN_F * OUT_F) + i * OUT_F;
    const float* av   = a + h * (2 * OUT_F) + which * OUT_F;
    float s = 0.f;
#pragma unroll 16
    for (int o = 0; o < OUT_F; o++) s += wrow[o] * av[o];
    g_v[which * 256 + h * 128 + i] = s;
}

// ---------------------------------------------------------------------------
// 2) per-node scores (one warp per node); also zeroes g_c
__global__ void __launch_bounds__(256) node_s_kernel(const float* __restrict__ x, int N) {
    __shared__ float vsm[512];
    int tid = threadIdx.x;
    vsm[tid]       = g_v[tid];
    vsm[tid + 256] = g_v[tid + 256];
    __syncthreads();

    int warp = tid >> 5, lane = tid & 31;
    int n = blockIdx.x * 8 + warp;
    if (n >= N) return;

    float4 xv = ((const float4*)x)[(size_t)n * 32 + lane];
    const float4* v4 = (const float4*)vsm;
    float4 vi0 = v4[lane];
    float4 vi1 = v4[32 + lane];
    float4 vj0 = v4[64 + lane];
    float4 vj1 = v4[96 + lane];

    float si0 = xv.x*vi0.x + xv.y*vi0.y + xv.z*vi0.z + xv.w*vi0.w;
    float si1 = xv.x*vi1.x + xv.y*vi1.y + xv.z*vi1.z + xv.w*vi1.w;
    float sj0 = xv.x*vj0.x + xv.y*vj0.y + xv.z*vj0.z + xv.w*vj0.w;
    float sj1 = xv.x*vj1.x + xv.y*vj1.y + xv.z*vj1.z + xv.w*vj1.w;

#pragma unroll
    for (int off = 16; off; off >>= 1) {
        si0 += __shfl_xor_sync(0xffffffffu, si0, off);
        si1 += __shfl_xor_sync(0xffffffffu, si1, off);
        sj0 += __shfl_xor_sync(0xffffffffu, sj0, off);
        sj1 += __shfl_xor_sync(0xffffffffu, sj1, off);
    }
    if (lane == 0) {
        g_si[n] = make_float2(si0, si1);
        g_sj[n] = make_float2(sj0, sj1);
        g_c[n]  = make_float2(0.f, 0.f);
    }
}

// ---------------------------------------------------------------------------
// 3) edge pass (round-2 measured form) + fused global-Z block reduction:
//    Z_h = sum over ALL edges of w_h, so accumulate locally and do one
//    block-level atomic -- eliminates the separate zred kernel.
__global__ void __launch_bounds__(256) edge_kernel(const int* __restrict__ ei, int E) {
    int k = blockIdx.x * blockDim.x + threadIdx.x;
    float z0 = 0.f, z1 = 0.f;
    if (k < E) {
        int src = __ldg(ei + k);
        int dst = __ldg(ei + E + k);
        float2 si = g_si[src];
        float2 sj = g_sj[dst];
        float e0 = si.x + sj.x;
        float e1 = si.y + sj.y;
        e0 = e0 > 0.f ? e0 : ALPHA * e0;
        e1 = e1 > 0.f ? e1 : ALPHA * e1;
        z0 = __expf(e0);
        z1 = __expf(e1);
        atomicAdd(&g_c[dst].x, z0);
        atomicAdd(&g_c[dst].y, z1);
    }
#pragma unroll
    for (int off = 16; off; off >>= 1) {
        z0 += __shfl_xor_sync(0xffffffffu, z0, off);
        z1 += __shfl_xor_sync(0xffffffffu, z1, off);
    }
    __shared__ float s0[8], s1[8];
    int warp = threadIdx.x >> 5, lane = threadIdx.x & 31;
    if (lane == 0) { s0[warp] = z0; s1[warp] = z1; }
    __syncthreads();
    if (threadIdx.x == 0) {
        float t0 = 0.f, t1 = 0.f;
#pragma unroll
        for (int w = 0; w < 8; w++) { t0 += s0[w]; t1 += s1[w]; }
        atomicAdd(&g_Z[0], t0);
        atomicAdd(&g_Z[1], t1);
    }
}

// ---------------------------------------------------------------------------
// 4) out = (x @ W) * c/Z  -- tf32 mma.sync GEMM.
//    Tile: 256 rows x 128 cols x K=128, 8 warps as 4(M)x2(N),
//    each warp 64x64 -> 4 m-frags x 8 n-frags of m16n8k8.
//    smem rows padded to 132 words: A-load banks (4g+t)%32 and B-load banks
//    (4t+g)%32 are both perfect permutations -> conflict-free.
#define XS_STRIDE 132
#define TILE_M    256

__device__ __forceinline__ unsigned f2tf32(float f) {
    unsigned u;
    asm("cvt.rna.tf32.f32 %0, %1;" : "=r"(u) : "f"(f));
    return u;
}

__device__ __forceinline__ void mma_tf32(float* d,
                                         unsigned a0, unsigned a1, unsigned a2, unsigned a3,
                                         unsigned b0, unsigned b1) {
    asm volatile("mma.sync.aligned.m16n8k8.row.col.f32.tf32.tf32.f32 "
                 "{%0,%1,%2,%3}, {%4,%5,%6,%7}, {%8,%9}, {%0,%1,%2,%3};"
                 : "+f"(d[0]), "+f"(d[1]), "+f"(d[2]), "+f"(d[3])
                 : "r"(a0), "r"(a1), "r"(a2), "r"(a3), "r"(b0), "r"(b1));
}

__global__ void __launch_bounds__(256, 1) out_gemm_kernel(const float* __restrict__ x,
                                                          const float* __restrict__ W,
                                                          float* __restrict__ out, int N) {
    extern __shared__ unsigned smem[];
    unsigned* xs = smem;                       // [256][132] tf32
    unsigned* ws = smem + TILE_M * XS_STRIDE;  // [128][132] tf32, col = h*64+o

    int tid = threadIdx.x;
    int n0 = blockIdx.x * TILE_M;

    // stage W: W[h][i][o] -> ws[i][h*64+o] (tf32)
    for (int idx = tid; idx < HEADS * IN_F * OUT_F; idx += 256) {
        int h = idx >> 13;
        int i = (idx >> 6) & 127;
        int o = idx & 63;
        ws[i * XS_STRIDE + h * 64 + o] = f2tf32(W[idx]);
    }
    // stage x tile (tf32, zero-padded past N)
    const float4* x4 = (const float4*)x;
    for (int idx = tid; idx < TILE_M * 32; idx += 256) {
        int r  = idx >> 5;
        int k4 = idx & 31;
        int n = n0 + r;
        float4 v = make_float4(0.f, 0.f, 0.f, 0.f);
        if (n < N) v = x4[(size_t)n * 32 + k4];
        uint4 u = make_uint4(f2tf32(v.x), f2tf32(v.y), f2tf32(v.z), f2tf32(v.w));
        *(uint4*)&xs[r * XS_STRIDE + k4 * 4] = u;
    }
    __syncthreads();

    int wid  = tid >> 5, lane = tid & 31;
    int wm   = wid >> 1;            // 0..3 : 64-row band
    int wn   = wid & 1;             // 0..1 : 64-col band (== head)
    int g    = lane >> 2;           // groupID
    int t    = lane & 3;            // threadID_in_group
    int cb   = wn * 64;

    float acc[4][8][4];
#pragma unroll
    for (int mi = 0; mi < 4; mi++)
#pragma unroll
        for (int ni = 0; ni < 8; ni++)
#pragma unroll
            for (int q = 0; q < 4; q++) acc[mi][ni][q] = 0.f;

#pragma unroll 2
    for (int ks = 0; ks < 16; ks++) {
        int k0 = ks * 8;
        unsigned av[4][4];
#pragma unroll
        for (int mi = 0; mi < 4; mi++) {
            int r0 = wm * 64 + mi * 16;
            av[mi][0] = xs[(r0 + g)     * XS_STRIDE + k0 + t];
            av[mi][1] = xs[(r0 + g + 8) * XS_STRIDE + k0 + t];
            av[mi][2] = xs[(r0 + g)     * XS_STRIDE + k0 + t + 4];
            av[mi][3] = xs[(r0 + g + 8) * XS_STRIDE + k0 + t + 4];
        }
        unsigned bv[8][2];
#pragma unroll
        for (int ni = 0; ni < 8; ni++) {
            int c = cb + ni * 8 + g;
            bv[ni][0] = ws[(k0 + t)     * XS_STRIDE + c];
            bv[ni][1] = ws[(k0 + t + 4) * XS_STRIDE + c];
        }
#pragma unroll
        for (int mi = 0; mi < 4; mi++)
#pragma unroll
            for (int ni = 0; ni < 8; ni++)
                mma_tf32(acc[mi][ni], av[mi][0], av[mi][1], av[mi][2], av[mi][3],
                         bv[ni][0], bv[ni][1]);
    }

    // epilogue: scale by c[n,head]/Z_head; head == wn
    float rz = 1.0f / g_Z[wn];
#pragma unroll
    for (int mi = 0; mi < 4; mi++) {
        int r0 = n0 + wm * 64 + mi * 16 + g;   // rows for c0,c1
        int r1 = r0 + 8;                        // rows for c2,c3
        float scl0 = 0.f, scl1 = 0.f;
        if (r0 < N) {
            float2 cc = g_c[r0];
            scl0 = (wn ? cc.y : cc.x) * rz;
        }
        if (r1 < N) {
            float2 cc = g_c[r1];
            scl1 = (wn ? cc.y : cc.x) * rz;
        }
#pragma unroll
        for (int ni = 0; ni < 8; ni++) {
            int col = cb + ni * 8 + 2 * t;
            if (r0 < N)
                *(float2*)&out[(size_t)r0 * 128 + col] =
                    make_float2(acc[mi][ni][0] * scl0, acc[mi][ni][1] * scl0);
            if (r1 < N)
                *(float2*)&out[(size_t)r1 * 128 + col] =
                    make_float2(acc[mi][ni][2] * scl1, acc[mi][ni][3] * scl1);
        }
    }
}

// ---------------------------------------------------------------------------
extern "C" void kernel_launch(void* const* d_in, const int* in_sizes, int n_in,
                              void* d_out, int out_size) {
    const float* x  = (const float*)d_in[0];
    const float* W  = (const float*)d_in[1];
    const float* a  = (const float*)d_in[2];
    const int*   ei = (const int*)d_in[3];
    float* out = (float*)d_out;

    int N = in_sizes[0] / IN_F;
    if (N > N_NODES) N = N_NODES;
    int E = in_sizes[3] / 2;

    prep_v_kernel<<<1, 512>>>(W, a);
    node_s_kernel<<<(N + 7) / 8, 256>>>(x, N);
    edge_kernel<<<(E + 255) / 256, 256>>>(ei, E);

    const int smem_bytes = (TILE_M + IN_F) * XS_STRIDE * 4;  // (256+128)*132*4 = 198KB
    cudaFuncSetAttribute(out_gemm_kernel,
                         cudaFuncAttributeMaxDynamicSharedMemorySize, smem_bytes);
    out_gemm_kernel<<<(N + TILE_M - 1) / TILE_M, 256, smem_bytes>>>(x, W, out, N);
}

// round 5
// speedup vs baseline: 1.5785x; 1.1333x over previous
#include <cuda_runtime.h>

#define N_NODES 50000
#define IN_F    128
#define OUT_F   64
#define HEADS   2
#define ALPHA   0.2f

__device__ float  g_v[512];          // [which(i/j)][head][128]
__device__ float2 g_si[N_NODES];
__device__ float2 g_sj[N_NODES];
__device__ float2 g_c[N_NODES];      // per-node sum of exp(e) per head
__device__ float  g_Z[2];            // global softmax denominator per head

// ---------------------------------------------------------------------------
// 1) v = W @ a (both halves, both heads); also zero g_Z
__global__ void prep_v_kernel(const float* __restrict__ W,
                              const float* __restrict__ a) {
    int t = threadIdx.x;            // 512 threads
    if (t < 2) g_Z[t] = 0.0f;
    int which = t >> 8;
    int h     = (t >> 7) & 1;
    int i     = t & 127;
    const float* wrow = W + h * (IN_F * OUT_F) + i * OUT_F;
    const float* av   = a + h * (2 * OUT_F) + which * OUT_F;
    float s = 0.f;
#pragma unroll 16
    for (int o = 0; o < OUT_F; o++) s += wrow[o] * av[o];
    g_v[which * 256 + h * 128 + i] = s;
}

// ---------------------------------------------------------------------------
// 2) per-node scores (one warp per node); also zeroes g_c
__global__ void __launch_bounds__(256) node_s_kernel(const float* __restrict__ x, int N) {
    __shared__ float vsm[512];
    int tid = threadIdx.x;
    vsm[tid]       = g_v[tid];
    vsm[tid + 256] = g_v[tid + 256];
    __syncthreads();

    int warp = tid >> 5, lane = tid & 31;
    int n = blockIdx.x * 8 + warp;
    if (n >= N) return;

    float4 xv = ((const float4*)x)[(size_t)n * 32 + lane];
    const float4* v4 = (const float4*)vsm;
    float4 vi0 = v4[lane];
    float4 vi1 = v4[32 + lane];
    float4 vj0 = v4[64 + lane];
    float4 vj1 = v4[96 + lane];

    float si0 = xv.x*vi0.x + xv.y*vi0.y + xv.z*vi0.z + xv.w*vi0.w;
    float si1 = xv.x*vi1.x + xv.y*vi1.y + xv.z*vi1.z + xv.w*vi1.w;
    float sj0 = xv.x*vj0.x + xv.y*vj0.y + xv.z*vj0.z + xv.w*vj0.w;
    float sj1 = xv.x*vj1.x + xv.y*vj1.y + xv.z*vj1.z + xv.w*vj1.w;

#pragma unroll
    for (int off = 16; off; off >>= 1) {
        si0 += __shfl_xor_sync(0xffffffffu, si0, off);
        si1 += __shfl_xor_sync(0xffffffffu, si1, off);
        sj0 += __shfl_xor_sync(0xffffffffu, sj0, off);
        sj1 += __shfl_xor_sync(0xffffffffu, sj1, off);
    }
    if (lane == 0) {
        g_si[n] = make_float2(si0, si1);
        g_sj[n] = make_float2(sj0, sj1);
        g_c[n]  = make_float2(0.f, 0.f);
    }
}

// ---------------------------------------------------------------------------
// 3) edge pass + fused global-Z reduction. ONE red.add.v2.f32 per edge
//    (3 L2 sector accesses/edge instead of 4).
__global__ void __launch_bounds__(256) edge_kernel(const int* __restrict__ ei, int E) {
    int k = blockIdx.x * blockDim.x + threadIdx.x;
    float z0 = 0.f, z1 = 0.f;
    if (k < E) {
        int src = __ldg(ei + k);
        int dst = __ldg(ei + E + k);
        float2 si = g_si[src];
        float2 sj = g_sj[dst];
        float e0 = si.x + sj.x;
        float e1 = si.y + sj.y;
        e0 = e0 > 0.f ? e0 : ALPHA * e0;
        e1 = e1 > 0.f ? e1 : ALPHA * e1;
        z0 = __expf(e0);
        z1 = __expf(e1);
        asm volatile("red.global.add.v2.f32 [%0], {%1, %2};"
                     :: "l"(&g_c[dst]), "f"(z0), "f"(z1) : "memory");
    }
#pragma unroll
    for (int off = 16; off; off >>= 1) {
        z0 += __shfl_xor_sync(0xffffffffu, z0, off);
        z1 += __shfl_xor_sync(0xffffffffu, z1, off);
    }
    __shared__ float s0[8], s1[8];
    int warp = threadIdx.x >> 5, lane = threadIdx.x & 31;
    if (lane == 0) { s0[warp] = z0; s1[warp] = z1; }
    __syncthreads();
    if (threadIdx.x == 0) {
        float t0 = 0.f, t1 = 0.f;
#pragma unroll
        for (int w = 0; w < 8; w++) { t0 += s0[w]; t1 += s1[w]; }
        asm volatile("red.global.add.v2.f32 [%0], {%1, %2};"
                     :: "l"(g_Z), "f"(t0), "f"(t1) : "memory");
    }
}

// ---------------------------------------------------------------------------
// 4) out = (x @ W) * c/Z  -- tf32 mma.sync GEMM, 512 threads (16 warps,
//    4/SMSP for latency hiding). Tile 256x128xK128; warps 8(M)x2(N), each
//    warp 32 rows x 64 cols = 2 m-frags x 8 n-frags of m16n8k8.
//    smem rows padded to 132 words (conflict-free for both A and B loads).
#define XS_STRIDE 132
#define TILE_M    256

__device__ __forceinline__ unsigned f2tf32(float f) {
    unsigned u;
    asm("cvt.rna.tf32.f32 %0, %1;" : "=r"(u) : "f"(f));
    return u;
}

__device__ __forceinline__ void mma_tf32(float* d,
                                         unsigned a0, unsigned a1, unsigned a2, unsigned a3,
                                         unsigned b0, unsigned b1) {
    asm volatile("mma.sync.aligned.m16n8k8.row.col.f32.tf32.tf32.f32 "
                 "{%0,%1,%2,%3}, {%4,%5,%6,%7}, {%8,%9}, {%0,%1,%2,%3};"
                 : "+f"(d[0]), "+f"(d[1]), "+f"(d[2]), "+f"(d[3])
                 : "r"(a0), "r"(a1), "r"(a2), "r"(a3), "r"(b0), "r"(b1));
}

__global__ void __launch_bounds__(512, 1) out_gemm_kernel(const float* __restrict__ x,
                                                          const float* __restrict__ W,
                                                          float* __restrict__ out, int N) {
    extern __shared__ unsigned smem[];
    unsigned* xs = smem;                       // [256][132] tf32
    unsigned* ws = smem + TILE_M * XS_STRIDE;  // [128][132] tf32, col = h*64+o

    int tid = threadIdx.x;
    int n0 = blockIdx.x * TILE_M;

    // stage W: W[h][i][o] -> ws[i][h*64+o] (tf32)
    for (int idx = tid; idx < HEADS * IN_F * OUT_F; idx += 512) {
        int h = idx >> 13;
        int i = (idx >> 6) & 127;
        int o = idx & 63;
        ws[i * XS_STRIDE + h * 64 + o] = f2tf32(W[idx]);
    }
    // stage x tile (tf32, zero-padded past N)
    const float4* x4 = (const float4*)x;
    for (int idx = tid; idx < TILE_M * 32; idx += 512) {
        int r  = idx >> 5;
        int k4 = idx & 31;
        int n = n0 + r;
        float4 v = make_float4(0.f, 0.f, 0.f, 0.f);
        if (n < N) v = x4[(size_t)n * 32 + k4];
        uint4 u = make_uint4(f2tf32(v.x), f2tf32(v.y), f2tf32(v.z), f2tf32(v.w));
        *(uint4*)&xs[r * XS_STRIDE + k4 * 4] = u;
    }
    __syncthreads();

    int wid  = tid >> 5, lane = tid & 31;
    int wm   = wid >> 1;            // 0..7 : 32-row band
    int wn   = wid & 1;             // 0..1 : 64-col band (== head)
    int g    = lane >> 2;           // groupID
    int t    = lane & 3;            // threadID_in_group
    int cb   = wn * 64;

    float acc[2][8][4];
#pragma unroll
    for (int mi = 0; mi < 2; mi++)
#pragma unroll
        for (int ni = 0; ni < 8; ni++)
#pragma unroll
            for (int q = 0; q < 4; q++) acc[mi][ni][q] = 0.f;

#pragma unroll 4
    for (int ks = 0; ks < 16; ks++) {
        int k0 = ks * 8;
        unsigned av[2][4];
#pragma unroll
        for (int mi = 0; mi < 2; mi++) {
            int r0 = wm * 32 + mi * 16;
            av[mi][0] = xs[(r0 + g)     * XS_STRIDE + k0 + t];
            av[mi][1] = xs[(r0 + g + 8) * XS_STRIDE + k0 + t];
            av[mi][2] = xs[(r0 + g)     * XS_STRIDE + k0 + t + 4];
            av[mi][3] = xs[(r0 + g + 8) * XS_STRIDE + k0 + t + 4];
        }
        unsigned bv[8][2];
#pragma unroll
        for (int ni = 0; ni < 8; ni++) {
            int c = cb + ni * 8 + g;
            bv[ni][0] = ws[(k0 + t)     * XS_STRIDE + c];
            bv[ni][1] = ws[(k0 + t + 4) * XS_STRIDE + c];
        }
#pragma unroll
        for (int mi = 0; mi < 2; mi++)
#pragma unroll
            for (int ni = 0; ni < 8; ni++)
                mma_tf32(acc[mi][ni], av[mi][0], av[mi][1], av[mi][2], av[mi][3],
                         bv[ni][0], bv[ni][1]);
    }

    // epilogue: scale by c[n,head]/Z_head; head == wn
    float rz = 1.0f / g_Z[wn];
#pragma unroll
    for (int mi = 0; mi < 2; mi++) {
        int r0 = n0 + wm * 32 + mi * 16 + g;   // rows for c0,c1
        int r1 = r0 + 8;                        // rows for c2,c3
        float scl0 = 0.f, scl1 = 0.f;
        if (r0 < N) {
            float2 cc = g_c[r0];
            scl0 = (wn ? cc.y : cc.x) * rz;
        }
        if (r1 < N) {
            float2 cc = g_c[r1];
            scl1 = (wn ? cc.y : cc.x) * rz;
        }
#pragma unroll
        for (int ni = 0; ni < 8; ni++) {
            int col = cb + ni * 8 + 2 * t;
            if (r0 < N)
                *(float2*)&out[(size_t)r0 * 128 + col] =
                    make_float2(acc[mi][ni][0] * scl0, acc[mi][ni][1] * scl0);
            if (r1 < N)
                *(float2*)&out[(size_t)r1 * 128 + col] =
                    make_float2(acc[mi][ni][2] * scl1, acc[mi][ni][3] * scl1);
        }
    }
}

// ---------------------------------------------------------------------------
extern "C" void kernel_launch(void* const* d_in, const int* in_sizes, int n_in,
                              void* d_out, int out_size) {
    const float* x  = (const float*)d_in[0];
    const float* W  = (const float*)d_in[1];
    const float* a  = (const float*)d_in[2];
    const int*   ei = (const int*)d_in[3];
    float* out = (float*)d_out;

    int N = in_sizes[0] / IN_F;
    if (N > N_NODES) N = N_NODES;
    int E = in_sizes[3] / 2;

    prep_v_kernel<<<1, 512>>>(W, a);
    node_s_kernel<<<(N + 7) / 8, 256>>>(x, N);
    edge_kernel<<<(E + 255) / 256, 256>>>(ei, E);

    const int smem_bytes = (TILE_M + IN_F) * XS_STRIDE * 4;  // (256+128)*132*4 = 198KB
    cudaFuncSetAttribute(out_gemm_kernel,
                         cudaFuncAttributeMaxDynamicSharedMemorySize, smem_bytes);
    out_gemm_kernel<<<(N + TILE_M - 1) / TILE_M, 512, smem_bytes>>>(x, W, out, N);
}

// round 7
// speedup vs baseline: 1.7416x; 1.1034x over previous
#include <cuda_runtime.h>

#define N_NODES 50000
#define IN_F    128
#define OUT_F   64
#define HEADS   2
#define ALPHA   0.2f

__device__ float  g_v[512];          // [which(i/j)][head][128]
__device__ float2 g_si[N_NODES];
__device__ float2 g_sj[N_NODES];
__device__ float2 g_c[N_NODES];      // per-node sum of exp(e) per head
__device__ float  g_Z[2];            // global softmax denominator per head

// ---------------------------------------------------------------------------
// 1) v = W @ a (both halves, both heads); also zero g_Z
__global__ void prep_v_kernel(const float* __restrict__ W,
                              const float* __restrict__ a) {
    int t = threadIdx.x;            // 512 threads
    if (t < 2) g_Z[t] = 0.0f;
    int which = t >> 8;
    int h     = (t >> 7) & 1;
    int i     = t & 127;
    const float* wrow = W + h * (IN_F * OUT_F) + i * OUT_F;
    const float* av   = a + h * (2 * OUT_F) + which * OUT_F;
    float s = 0.f;
#pragma unroll 16
    for (int o = 0; o < OUT_F; o++) s += wrow[o] * av[o];
    g_v[which * 256 + h * 128 + i] = s;
}

// ---------------------------------------------------------------------------
// 2) per-node scores (one warp per node); also zeroes g_c
__global__ void __launch_bounds__(256) node_s_kernel(const float* __restrict__ x, int N) {
    __shared__ float vsm[512];
    int tid = threadIdx.x;
    vsm[tid]       = g_v[tid];
    vsm[tid + 256] = g_v[tid + 256];
    __syncthreads();

    int warp = tid >> 5, lane = tid & 31;
    int n = blockIdx.x * 8 + warp;
    if (n >= N) return;

    float4 xv = ((const float4*)x)[(size_t)n * 32 + lane];
    const float4* v4 = (const float4*)vsm;
    float4 vi0 = v4[lane];
    float4 vi1 = v4[32 + lane];
    float4 vj0 = v4[64 + lane];
    float4 vj1 = v4[96 + lane];

    float si0 = xv.x*vi0.x + xv.y*vi0.y + xv.z*vi0.z + xv.w*vi0.w;
    float si1 = xv.x*vi1.x + xv.y*vi1.y + xv.z*vi1.z + xv.w*vi1.w;
    float sj0 = xv.x*vj0.x + xv.y*vj0.y + xv.z*vj0.z + xv.w*vj0.w;
    float sj1 = xv.x*vj1.x + xv.y*vj1.y + xv.z*vj1.z + xv.w*vj1.w;

#pragma unroll
    for (int off = 16; off; off >>= 1) {
        si0 += __shfl_xor_sync(0xffffffffu, si0, off);
        si1 += __shfl_xor_sync(0xffffffffu, si1, off);
        sj0 += __shfl_xor_sync(0xffffffffu, sj0, off);
        sj1 += __shfl_xor_sync(0xffffffffu, sj1, off);
    }
    if (lane == 0) {
        g_si[n] = make_float2(si0, si1);
        g_sj[n] = make_float2(sj0, sj1);
        g_c[n]  = make_float2(0.f, 0.f);
    }
}

// ---------------------------------------------------------------------------
// 3) edge pass + fused global-Z reduction (frozen: measured win)
__global__ void __launch_bounds__(256) edge_kernel(const int* __restrict__ ei, int E) {
    int k = blockIdx.x * blockDim.x + threadIdx.x;
    float z0 = 0.f, z1 = 0.f;
    if (k < E) {
        int src = __ldg(ei + k);
        int dst = __ldg(ei + E + k);
        float2 si = g_si[src];
        float2 sj = g_sj[dst];
        float e0 = si.x + sj.x;
        float e1 = si.y + sj.y;
        e0 = e0 > 0.f ? e0 : ALPHA * e0;
        e1 = e1 > 0.f ? e1 : ALPHA * e1;
        z0 = __expf(e0);
        z1 = __expf(e1);
        asm volatile("red.global.add.v2.f32 [%0], {%1, %2};"
                     :: "l"(&g_c[dst]), "f"(z0), "f"(z1) : "memory");
    }
#pragma unroll
    for (int off = 16; off; off >>= 1) {
        z0 += __shfl_xor_sync(0xffffffffu, z0, off);
        z1 += __shfl_xor_sync(0xffffffffu, z1, off);
    }
    __shared__ float s0[8], s1[8];
    int warp = threadIdx.x >> 5, lane = threadIdx.x & 31;
    if (lane == 0) { s0[warp] = z0; s1[warp] = z1; }
    __syncthreads();
    if (threadIdx.x == 0) {
        float t0 = 0.f, t1 = 0.f;
#pragma unroll
        for (int w = 0; w < 8; w++) { t0 += s0[w]; t1 += s1[w]; }
        asm volatile("red.global.add.v2.f32 [%0], {%1, %2};"
                     :: "l"(g_Z), "f"(t0), "f"(t1) : "memory");
    }
}

// ---------------------------------------------------------------------------
// 4) out = (x @ W) * c/Z  -- tf32 mma.sync, PERSISTENT.
//    148 CTAs stride over 391 tiles of 128 rows. 256 threads = 8 warps as
//    4(M)x2(N); warp = 32 rows x 64 cols = 2 m-frags x 8 n-frags m16n8k8.
//    W staged ONCE per CTA, TRANSPOSED: ws[c][k] -> B-load bank (4g+t+4c0)%32
//    is a perfect lane permutation (old layout had 2-way conflicts on all
//    B loads). A-load bank (4(r0+g)+t)%32 also a permutation.
#define XS_STRIDE 132
#define TILE_M    128
#define NTILES    ((N_NODES + TILE_M - 1) / TILE_M)

__device__ __forceinline__ unsigned f2tf32(float f) {
    unsigned u;
    asm("cvt.rna.tf32.f32 %0, %1;" : "=r"(u) : "f"(f));
    return u;
}

__device__ __forceinline__ void mma_tf32(float* d,
                                         unsigned a0, unsigned a1, unsigned a2, unsigned a3,
                                         unsigned b0, unsigned b1) {
    asm volatile("mma.sync.aligned.m16n8k8.row.col.f32.tf32.tf32.f32 "
                 "{%0,%1,%2,%3}, {%4,%5,%6,%7}, {%8,%9}, {%0,%1,%2,%3};"
                 : "+f"(d[0]), "+f"(d[1]), "+f"(d[2]), "+f"(d[3])
                 : "r"(a0), "r"(a1), "r"(a2), "r"(a3), "r"(b0), "r"(b1));
}

__global__ void __launch_bounds__(256, 1) out_gemm_kernel(const float* __restrict__ x,
                                                          const float* __restrict__ W,
                                                          float* __restrict__ out,
                                                          int N, int numTiles) {
    extern __shared__ unsigned smem[];
    unsigned* xs = smem;                       // [128][132] tf32, xs[r][k]
    unsigned* ws = smem + TILE_M * XS_STRIDE;  // [128][132] tf32 TRANSPOSED: ws[c][k]

    int tid = threadIdx.x;

    // stage W once: W[h][i][o] -> ws[(h*64+o)*XS + i]
    for (int idx = tid; idx < HEADS * IN_F * OUT_F; idx += 256) {
        int h = idx >> 13;
        int i = (idx >> 6) & 127;
        int o = idx & 63;
        ws[(h * 64 + o) * XS_STRIDE + i] = f2tf32(W[idx]);
    }

    int wid  = tid >> 5, lane = tid & 31;
    int wm   = wid >> 1;            // 0..3 : 32-row band
    int wn   = wid & 1;             // 0..1 : 64-col band (== head)
    int g    = lane >> 2;           // groupID
    int t    = lane & 3;            // threadID_in_group
    int cb   = wn * 64;
    float rz = 1.0f / g_Z[wn];

    const float4* x4 = (const float4*)x;

    for (int tile = blockIdx.x; tile < numTiles; tile += gridDim.x) {
        int n0 = tile * TILE_M;
        __syncthreads();    // previous iteration's xs readers are done

        // stage x tile (tf32, zero-padded past N)
        for (int idx = tid; idx < TILE_M * 32; idx += 256) {
            int r  = idx >> 5;
            int k4 = idx & 31;
            int n = n0 + r;
            float4 v = make_float4(0.f, 0.f, 0.f, 0.f);
            if (n < N) v = x4[(size_t)n * 32 + k4];
            uint4 u = make_uint4(f2tf32(v.x), f2tf32(v.y), f2tf32(v.z), f2tf32(v.w));
            *(uint4*)&xs[r * XS_STRIDE + k4 * 4] = u;
        }
        __syncthreads();

        float acc[2][8][4];
#pragma unroll
        for (int mi = 0; mi < 2; mi++)
#pragma unroll
            for (int ni = 0; ni < 8; ni++)
#pragma unroll
                for (int q = 0; q < 4; q++) acc[mi][ni][q] = 0.f;

#pragma unroll 4
        for (int ks = 0; ks < 16; ks++) {
            int k0 = ks * 8;
            unsigned av[2][4];
#pragma unroll
            for (int mi = 0; mi < 2; mi++) {
                int r0 = wm * 32 + mi * 16;
                av[mi][0] = xs[(r0 + g)     * XS_STRIDE + k0 + t];
                av[mi][1] = xs[(r0 + g + 8) * XS_STRIDE + k0 + t];
                av[mi][2] = xs[(r0 + g)     * XS_STRIDE + k0 + t + 4];
                av[mi][3] = xs[(r0 + g + 8) * XS_STRIDE + k0 + t + 4];
            }
            unsigned bv[8][2];
#pragma unroll
            for (int ni = 0; ni < 8; ni++) {
                int c = cb + ni * 8 + g;
                bv[ni][0] = ws[c * XS_STRIDE + k0 + t];
                bv[ni][1] = ws[c * XS_STRIDE + k0 + t + 4];
            }
#pragma unroll
            for (int mi = 0; mi < 2; mi++)
#pragma unroll
                for (int ni = 0; ni < 8; ni++)
                    mma_tf32(acc[mi][ni], av[mi][0], av[mi][1], av[mi][2], av[mi][3],
                             bv[ni][0], bv[ni][1]);
        }

        // epilogue: scale by c[n,head]/Z_head; head == wn
#pragma unroll
        for (int mi = 0; mi < 2; mi++) {
            int r0 = n0 + wm * 32 + mi * 16 + g;   // rows for c0,c1
            int r1 = r0 + 8;                        // rows for c2,c3
            float scl0 = 0.f, scl1 = 0.f;
            if (r0 < N) {
                float2 cc = g_c[r0];
                scl0 = (wn ? cc.y : cc.x) * rz;
            }
            if (r1 < N) {
                float2 cc = g_c[r1];
                scl1 = (wn ? cc.y : cc.x) * rz;
            }
#pragma unroll
            for (int ni = 0; ni < 8; ni++) {
                int col = cb + ni * 8 + 2 * t;
                if (r0 < N)
                    *(float2*)&out[(size_t)r0 * 128 + col] =
                        make_float2(acc[mi][ni][0] * scl0, acc[mi][ni][1] * scl0);
                if (r1 < N)
                    *(float2*)&out[(size_t)r1 * 128 + col] =
                        make_float2(acc[mi][ni][2] * scl1, acc[mi][ni][3] * scl1);
            }
        }
    }
}

// ---------------------------------------------------------------------------
extern "C" void kernel_launch(void* const* d_in, const int* in_sizes, int n_in,
                              void* d_out, int out_size) {
    const float* x  = (const float*)d_in[0];
    const float* W  = (const float*)d_in[1];
    const float* a  = (const float*)d_in[2];
    const int*   ei = (const int*)d_in[3];
    float* out = (float*)d_out;

    int N = in_sizes[0] / IN_F;
    if (N > N_NODES) N = N_NODES;
    int E = in_sizes[3] / 2;
    int numTiles = (N + TILE_M - 1) / TILE_M;

    prep_v_kernel<<<1, 512>>>(W, a);
    node_s_kernel<<<(N + 7) / 8, 256>>>(x, N);
    edge_kernel<<<(E + 255) / 256, 256>>>(ei, E);

    const int smem_bytes = 2 * IN_F * XS_STRIDE * 4;  // 256*132*4 = 132KB
    cudaFuncSetAttribute(out_gemm_kernel,
                         cudaFuncAttributeMaxDynamicSharedMemorySize, smem_bytes);
    int grid = numTiles < 148 ? numTiles : 148;
    out_gemm_kernel<<<grid, 256, smem_bytes>>>(x, W, out, N, numTiles);
}